// round 13
// baseline (speedup 1.0000x reference)
#include <cuda_runtime.h>
#include <math.h>
#include <stdint.h>

#define NN   20000
#define NE   320000
#define NG   64
#define DIN  1280
#define DH   512
#define DFC  1024
#define DOUT 5000

// ---------------- scratch ----------------
__device__ uint16_t g_xbf  [NN * DIN];
__device__ uint16_t g_w1bf [DIN * DH];
__device__ uint16_t g_w2bf [DH * DH];
__device__ uint16_t g_hbf  [NN * DH];   // GEMM1 out; later reused as gather2 out
__device__ uint16_t g_aggbf[NN * DH];
__device__ uint16_t g_h2bf [NN * DH];
__device__ float    g_dinv [NN];
__device__ int      g_cnt  [NN];
__device__ int      g_rowptr[NN + 1];
__device__ int      g_cursor[NN];
__device__ int      g_csrsrc[NE];
__device__ float    g_pool[NG * DH];
__device__ float    g_fc1 [NG * DFC];
__device__ int      g_is64;

// ---------------- helpers ----------------
__device__ __forceinline__ uint32_t smem_u32(const void* p) {
    uint32_t a;
    asm("{ .reg .u64 t; cvta.to.shared.u64 t, %1; cvt.u32.u64 %0, t; }" : "=r"(a) : "l"(p));
    return a;
}
__device__ __forceinline__ uint32_t pack_bf16(float lo, float hi) {
    uint32_t r;
    asm("cvt.rn.bf16x2.f32 %0, %1, %2;" : "=r"(r) : "f"(hi), "f"(lo));
    return r;
}
__device__ __forceinline__ float bf_lo(uint32_t u) { return __uint_as_float(u << 16); }
__device__ __forceinline__ float bf_hi(uint32_t u) { return __uint_as_float(u & 0xFFFF0000u); }

__device__ __forceinline__ void ldsm_x4(uint32_t* r, uint32_t addr) {
    asm volatile("ldmatrix.sync.aligned.m8n8.x4.shared.b16 {%0,%1,%2,%3}, [%4];"
        : "=r"(r[0]), "=r"(r[1]), "=r"(r[2]), "=r"(r[3]) : "r"(addr));
}
__device__ __forceinline__ void ldsm_x2t(uint32_t* r, uint32_t addr) {
    asm volatile("ldmatrix.sync.aligned.m8n8.x2.trans.shared.b16 {%0,%1}, [%2];"
        : "=r"(r[0]), "=r"(r[1]) : "r"(addr));
}
__device__ __forceinline__ void cpa16(uint32_t dst, const void* src, int valid) {
    asm volatile("cp.async.cg.shared.global [%0], [%1], 16, %2;"
        :: "r"(dst), "l"(src), "r"(valid ? 16 : 0));
}
#define CPA_COMMIT() asm volatile("cp.async.commit_group;" ::: "memory")
#define CPA_WAIT1()  asm volatile("cp.async.wait_group 1;" ::: "memory")

// ---------------- fused f32 -> bf16 conversion ----------------
#define N4_X  (NN * DIN / 4)
#define N4_W1 (DIN * DH / 4)
#define N4_W2 (DH * DH / 4)
#define N4_ALL (N4_X + N4_W1 + N4_W2)

__global__ void k_cvt_all(const float4* __restrict__ x,
                          const float4* __restrict__ w1,
                          const float4* __restrict__ w2)
{
    int i = blockIdx.x * blockDim.x + threadIdx.x;
    if (i >= N4_ALL) return;
    const float4* src;
    uint2* dst;
    int off;
    if (i < N4_X) {
        src = x;  dst = (uint2*)g_xbf;  off = i;
    } else if (i < N4_X + N4_W1) {
        src = w1; dst = (uint2*)g_w1bf; off = i - N4_X;
    } else {
        src = w2; dst = (uint2*)g_w2bf; off = i - N4_X - N4_W1;
    }
    float4 v = src[off];
    dst[off] = make_uint2(pack_bf16(v.x, v.y), pack_bf16(v.z, v.w));
}

// ---------------- dtype detection ----------------
__global__ void k_detect(const void* ei) {
    const long long* p = (const long long*)ei;
    int ok = 1;
#pragma unroll
    for (int i = 0; i < 8; i++) {
        long long v = p[i];
        if (v < 0 || v >= NN) ok = 0;
    }
    g_is64 = ok;
}
__device__ __forceinline__ int idx_at(const void* p, long long i) {
    return g_is64 ? (int)((const long long*)p)[i] : ((const int*)p)[i];
}

// ---------------- degree / CSR ----------------
__global__ void k_zero_cnt() {
    int i = blockIdx.x * blockDim.x + threadIdx.x;
    if (i < NN) g_cnt[i] = 0;
}
__global__ void k_deg(const void* __restrict__ ei) {
    int e = blockIdx.x * blockDim.x + threadIdx.x;
    if (e < NE) atomicAdd(&g_cnt[idx_at(ei, (long long)NE + e)], 1);
}

#define SCAN_T   1024
#define SCAN_CH  20
__global__ void __launch_bounds__(SCAN_T) k_scan() {
    __shared__ int s[SCAN_T];
    int tid = threadIdx.x;
    int base = tid * SCAN_CH;
    int local[SCAN_CH];
    int cnts[SCAN_CH];
    int sum = 0;
#pragma unroll
    for (int i = 0; i < SCAN_CH; i++) {
        int idx = base + i;
        int v = (idx < NN) ? g_cnt[idx] : 0;
        cnts[i] = v;
        local[i] = sum;
        sum += v;
    }
    s[tid] = sum;
    __syncthreads();
    for (int off = 1; off < SCAN_T; off <<= 1) {
        int v = (tid >= off) ? s[tid - off] : 0;
        __syncthreads();
        if (tid >= off) s[tid] += v;
        __syncthreads();
    }
    int pre = (tid > 0) ? s[tid - 1] : 0;
#pragma unroll
    for (int i = 0; i < SCAN_CH; i++) {
        int idx = base + i;
        if (idx < NN) {
            int v = pre + local[i];
            g_rowptr[idx] = v;
            g_cursor[idx] = v;
            g_dinv[idx] = rsqrtf((float)cnts[i] + 1.0f);
        }
    }
    if (tid == SCAN_T - 1) g_rowptr[NN] = NE;
}
__global__ void k_fill(const void* __restrict__ ei) {
    int e = blockIdx.x * blockDim.x + threadIdx.x;
    if (e < NE) {
        int src, dst;
        if (g_is64) {
            const long long* p = (const long long*)ei;
            src = (int)p[e]; dst = (int)p[NE + e];
        } else {
            const int* p = (const int*)ei;
            src = p[e]; dst = p[NE + e];
        }
        g_csrsrc[atomicAdd(&g_cursor[dst], 1)] = src;
    }
}

// ---------------- bf16 mma GEMM, cp.async 3-stage pipeline, BK=64 ----------------
#define A_STR 72     // halves; 8-row ldmatrix stride 144B mod 128 = 16 -> conflict-free
#define B_STR 136
#define ABYTES (128 * A_STR * 2)             // 18432
#define BBYTES (64 * B_STR * 2)              // 17408
#define STG    (ABYTES + BBYTES)             // 35840
#define GEMM_SMEM (3 * STG)                  // 107520

__global__ void __launch_bounds__(256, 2) k_gemm_bf16(
    const uint16_t* __restrict__ A, const uint16_t* __restrict__ B,
    uint16_t* __restrict__ Cb, int M, int K)
{
    extern __shared__ __align__(16) uint16_t smem[];
    const uint32_t sb = smem_u32(smem);

    const int tid  = threadIdx.x;
    const int wid  = tid >> 5;
    const int lane = tid & 31;
    const int wm   = wid >> 2;
    const int wn   = wid & 3;
    const int n0   = blockIdx.x * 128;
    const int m0   = blockIdx.y * 128;
    const int NIT  = K >> 6;

    // loaders: A 128 rows x 64 halves (2 thr/row, 4x16B each);
    //          B 64 rows x 128 halves (4 thr/row, 4x16B each)
    const int ar0 = tid >> 1;
    const int ac0 = (tid & 1) * 32;   // halves
    const int br0 = tid >> 2;
    const int bc0 = (tid & 3) * 32;   // halves

    auto load_tile = [&](int it, int stage) {
        const int k0 = it << 6;
        const uint32_t base = sb + stage * STG;
        const int avalid = (m0 + ar0) < M;
        const uint16_t* asrc = A + (size_t)(m0 + ar0) * K + k0 + ac0;
        uint32_t adst = base + ar0 * (A_STR * 2) + ac0 * 2;
#pragma unroll
        for (int i = 0; i < 4; i++)
            cpa16(adst + i * 16, asrc + i * 8, avalid);
        const uint16_t* bsrc = B + (size_t)(k0 + br0) * DH + n0 + bc0;
        uint32_t bdst = base + ABYTES + br0 * (B_STR * 2) + bc0 * 2;
#pragma unroll
        for (int i = 0; i < 4; i++)
            cpa16(bdst + i * 16, bsrc + i * 8, 1);
    };

    float acc[4][4][4];
#pragma unroll
    for (int mi = 0; mi < 4; mi++)
#pragma unroll
        for (int ni = 0; ni < 4; ni++)
#pragma unroll
            for (int q = 0; q < 4; q++) acc[mi][ni][q] = 0.0f;

    load_tile(0, 0);
    CPA_COMMIT();
    if (NIT > 1) load_tile(1, 1);
    CPA_COMMIT();

    const int lr15 = lane & 15;
    const int lk8  = (lane >> 4) << 3;

    for (int it = 0; it < NIT; it++) {
        CPA_WAIT1();
        __syncthreads();

        int nxt = it + 2;
        if (nxt < NIT) load_tile(nxt, nxt % 3);
        CPA_COMMIT();

        const uint32_t aB = sb + (it % 3) * STG;
        const uint32_t bB = aB + ABYTES;

#pragma unroll
        for (int ks = 0; ks < 4; ks++) {
            const int kb = ks * 16;
            uint32_t af[4][4], bfr[4][2];
#pragma unroll
            for (int mi = 0; mi < 4; mi++) {
                uint32_t ad = aB +
                    (uint32_t)(((wm * 64 + mi * 16 + lr15) * A_STR + kb + lk8) * 2);
                ldsm_x4(af[mi], ad);
            }
#pragma unroll
            for (int ni = 0; ni < 4; ni++) {
                uint32_t bd = bB +
                    (uint32_t)(((kb + lr15) * B_STR + wn * 32 + ni * 8) * 2);
                ldsm_x2t(bfr[ni], bd);
            }
#pragma unroll
            for (int mi = 0; mi < 4; mi++)
#pragma unroll
                for (int ni = 0; ni < 4; ni++) {
                    asm volatile(
                        "mma.sync.aligned.m16n8k16.row.col.f32.bf16.bf16.f32 "
                        "{%0,%1,%2,%3}, {%4,%5,%6,%7}, {%8,%9}, {%0,%1,%2,%3};"
                        : "+f"(acc[mi][ni][0]), "+f"(acc[mi][ni][1]),
                          "+f"(acc[mi][ni][2]), "+f"(acc[mi][ni][3])
                        : "r"(af[mi][0]), "r"(af[mi][1]), "r"(af[mi][2]), "r"(af[mi][3]),
                          "r"(bfr[ni][0]), "r"(bfr[ni][1]));
                }
        }
    }

    const int r = lane >> 2;
    const int c = lane & 3;
#pragma unroll
    for (int mi = 0; mi < 4; mi++) {
        int row = m0 + wm * 64 + mi * 16 + r;
#pragma unroll
        for (int ni = 0; ni < 4; ni++) {
            int col = n0 + wn * 32 + ni * 8 + c * 2;
            if (row < M)
                *(uint32_t*)(Cb + (size_t)row * DH + col) =
                    pack_bf16(acc[mi][ni][0], acc[mi][ni][1]);
            if (row + 8 < M)
                *(uint32_t*)(Cb + (size_t)(row + 8) * DH + col) =
                    pack_bf16(acc[mi][ni][2], acc[mi][ni][3]);
        }
    }
}

// ---------------- CSR gather (bf16 in, bf16+relu out), 8-way unrolled ----------------
__global__ void __launch_bounds__(256) k_gather(
    const uint16_t* __restrict__ h, const float* __restrict__ bias,
    uint16_t* __restrict__ ob)
{
    int n = blockIdx.x * 2 + threadIdx.y;
    if (n >= NN) return;
    int s = g_rowptr[n];
    int e = g_rowptr[n + 1];
    float dn = g_dinv[n];
    int c = threadIdx.x * 4;

    uint2 u = *(const uint2*)(h + (size_t)n * DH + c);
    float d2 = dn * dn;
    float a0 = bf_lo(u.x) * d2, a1 = bf_hi(u.x) * d2;
    float a2 = bf_lo(u.y) * d2, a3 = bf_hi(u.y) * d2;

    int j = s;
    for (; j + 7 < e; j += 8) {
        int sv[8];
        float cv[8];
        uint2 uv[8];
#pragma unroll
        for (int q = 0; q < 8; q++) sv[q] = g_csrsrc[j + q];
#pragma unroll
        for (int q = 0; q < 8; q++) cv[q] = g_dinv[sv[q]] * dn;
#pragma unroll
        for (int q = 0; q < 8; q++)
            uv[q] = *(const uint2*)(h + (size_t)sv[q] * DH + c);
#pragma unroll
        for (int q = 0; q < 8; q++) {
            a0 = fmaf(bf_lo(uv[q].x), cv[q], a0);
            a1 = fmaf(bf_hi(uv[q].x), cv[q], a1);
            a2 = fmaf(bf_lo(uv[q].y), cv[q], a2);
            a3 = fmaf(bf_hi(uv[q].y), cv[q], a3);
        }
    }
    for (; j < e; j++) {
        int s0 = g_csrsrc[j];
        float c0 = g_dinv[s0] * dn;
        uint2 u0 = *(const uint2*)(h + (size_t)s0 * DH + c);
        a0 = fmaf(bf_lo(u0.x), c0, a0); a1 = fmaf(bf_hi(u0.x), c0, a1);
        a2 = fmaf(bf_lo(u0.y), c0, a2); a3 = fmaf(bf_hi(u0.y), c0, a3);
    }

    float4 b = *(const float4*)(bias + c);
    a0 = fmaxf(a0 + b.x, 0.f); a1 = fmaxf(a1 + b.y, 0.f);
    a2 = fmaxf(a2 + b.z, 0.f); a3 = fmaxf(a3 + b.w, 0.f);
    *(uint2*)(ob + (size_t)n * DH + c) =
        make_uint2(pack_bf16(a0, a1), pack_bf16(a2, a3));
}

// ---------------- segment max over bf16 rows ----------------
__device__ __forceinline__ int lower_bound_batch(const void* batch, int val) {
    int lo = 0, hi = NN;
    while (lo < hi) {
        int mid = (lo + hi) >> 1;
        if (idx_at(batch, mid) < val) lo = mid + 1; else hi = mid;
    }
    return lo;
}
// grid (NG, 2), 128 thr; each thread = one uint32 (2 cols)
__global__ void k_segmax(const void* __restrict__ batch, const uint16_t* __restrict__ hb) {
    int g = blockIdx.x;
    int cw = blockIdx.y * 128 + threadIdx.x;   // word index 0..255
    int s = lower_bound_batch(batch, g);
    int e = lower_bound_batch(batch, g + 1);
    const uint32_t* hw = (const uint32_t*)hb;
    float m0 = 0.f, m1 = 0.f, m2 = 0.f, m3 = 0.f;
    int n = s;
    for (; n + 1 < e; n += 2) {
        uint32_t u0 = hw[(size_t)n * (DH / 2) + cw];
        uint32_t u1 = hw[(size_t)(n + 1) * (DH / 2) + cw];
        m0 = fmaxf(m0, bf_lo(u0)); m1 = fmaxf(m1, bf_hi(u0));
        m2 = fmaxf(m2, bf_lo(u1)); m3 = fmaxf(m3, bf_hi(u1));
    }
    if (n < e) {
        uint32_t u0 = hw[(size_t)n * (DH / 2) + cw];
        m0 = fmaxf(m0, bf_lo(u0)); m1 = fmaxf(m1, bf_hi(u0));
    }
    g_pool[g * DH + cw * 2]     = fmaxf(m0, m2);
    g_pool[g * DH + cw * 2 + 1] = fmaxf(m1, m3);
}

// ---------------- FC head ----------------
__global__ void __launch_bounds__(256) k_head(
    const float* __restrict__ A, const float* __restrict__ B,
    const float* __restrict__ bias, float* __restrict__ C,
    int N, int K, int mode,
    const float* __restrict__ gamma, const float* __restrict__ beta)
{
    const int BKh = 32, BNh = 32;
    __shared__ float As[BKh][64];
    __shared__ float Bs[BKh][BNh];

    int tid = threadIdx.x;
    int colBase = blockIdx.x * BNh;
    int ty = tid >> 4, tx = tid & 15;

    float acc[4][2] = {{0.f, 0.f}, {0.f, 0.f}, {0.f, 0.f}, {0.f, 0.f}};

    for (int k0 = 0; k0 < K; k0 += BKh) {
        __syncthreads();
#pragma unroll
        for (int l = 0; l < 8; l++) {
            int idx = tid * 8 + l;
            int m = idx >> 5, k = idx & 31;
            As[k][m] = A[(size_t)m * K + k0 + k];
        }
#pragma unroll
        for (int l = 0; l < 4; l++) {
            int idx = tid * 4 + l;
            int k = idx >> 5, n = idx & 31;
            int col = colBase + n;
            Bs[k][n] = (col < N) ? B[(size_t)(k0 + k) * N + col] : 0.f;
        }
        __syncthreads();
#pragma unroll
        for (int k = 0; k < BKh; k++) {
            float ra2[4], rb2[2];
#pragma unroll
            for (int i = 0; i < 4; i++) ra2[i] = As[k][ty * 4 + i];
#pragma unroll
            for (int j = 0; j < 2; j++) rb2[j] = Bs[k][tx * 2 + j];
#pragma unroll
            for (int i = 0; i < 4; i++)
#pragma unroll
                for (int j = 0; j < 2; j++)
                    acc[i][j] = fmaf(ra2[i], rb2[j], acc[i][j]);
        }
    }

    const float bninv = rsqrtf(1.0f + 1e-5f);
#pragma unroll
    for (int i = 0; i < 4; i++) {
#pragma unroll
        for (int j = 0; j < 2; j++) {
            int row = ty * 4 + i;
            int col = colBase + tx * 2 + j;
            if (col < N) {
                float z = acc[i][j] + bias[col];
                if (mode == 0) {
                    z = fmaxf(z, 0.f);
                } else {
                    z = z * gamma[col] * bninv + beta[col];
                    z = 1.0f / (1.0f + expf(-z));
                }
                C[(size_t)row * N + col] = z;
            }
        }
    }
}

// ---------------- host ----------------
extern "C" void kernel_launch(void* const* d_in, const int* in_sizes, int n_in,
                              void* d_out, int out_size)
{
    const float* x     = (const float*)d_in[0];
    const void*  ei    = d_in[1];
    const void*  batch = d_in[2];
    const float* Wg1   = (const float*)d_in[3];
    const float* bg1   = (const float*)d_in[4];
    const float* Wg2   = (const float*)d_in[5];
    const float* bg2   = (const float*)d_in[6];
    const float* W1    = (const float*)d_in[7];
    const float* b1    = (const float*)d_in[8];
    const float* W2    = (const float*)d_in[9];
    const float* b2    = (const float*)d_in[10];
    const float* gamma = (const float*)d_in[11];
    const float* beta  = (const float*)d_in[12];
    float* out = (float*)d_out;

    uint16_t *p_xbf, *p_w1bf, *p_w2bf, *p_hbf, *p_aggbf, *p_h2bf;
    float *p_pool, *p_fc1;
    cudaGetSymbolAddress((void**)&p_xbf,   g_xbf);
    cudaGetSymbolAddress((void**)&p_w1bf,  g_w1bf);
    cudaGetSymbolAddress((void**)&p_w2bf,  g_w2bf);
    cudaGetSymbolAddress((void**)&p_hbf,   g_hbf);
    cudaGetSymbolAddress((void**)&p_aggbf, g_aggbf);
    cudaGetSymbolAddress((void**)&p_h2bf,  g_h2bf);
    cudaGetSymbolAddress((void**)&p_pool,  g_pool);
    cudaGetSymbolAddress((void**)&p_fc1,   g_fc1);

    cudaFuncSetAttribute(k_gemm_bf16,
        cudaFuncAttributeMaxDynamicSharedMemorySize, GEMM_SMEM);

    static cudaStream_t sB = nullptr;
    static cudaEvent_t evFork = nullptr, evJoin = nullptr;
    if (!sB) {
        cudaStreamCreateWithFlags(&sB, cudaStreamNonBlocking);
        cudaEventCreateWithFlags(&evFork, cudaEventDisableTiming);
        cudaEventCreateWithFlags(&evJoin, cudaEventDisableTiming);
    }

    // ---- fork: CSR build chain on sB, concurrent with cvt+GEMM1 on main ----
    cudaEventRecord(evFork, 0);
    cudaStreamWaitEvent(sB, evFork, 0);

    k_detect<<<1, 1, 0, sB>>>(ei);
    k_zero_cnt<<<(NN + 255) / 256, 256, 0, sB>>>();
    k_deg<<<(NE + 255) / 256, 256, 0, sB>>>(ei);
    k_scan<<<1, SCAN_T, 0, sB>>>();
    k_fill<<<(NE + 255) / 256, 256, 0, sB>>>(ei);
    cudaEventRecord(evJoin, sB);

    // main stream: conversions + GEMM1 (independent of CSR)
    k_cvt_all<<<(N4_ALL + 255) / 256, 256>>>((const float4*)x, (const float4*)Wg1,
                                             (const float4*)Wg2);
    dim3 gg(DH / 128, (NN + 127) / 128);
    k_gemm_bf16<<<gg, 256, GEMM_SMEM>>>(p_xbf, p_w1bf, p_hbf, NN, DIN);

    // ---- join ----
    cudaStreamWaitEvent(0, evJoin, 0);

    k_gather<<<(NN + 1) / 2, dim3(128, 2)>>>(p_hbf, bg1, p_aggbf);
    k_gemm_bf16<<<gg, 256, GEMM_SMEM>>>(p_aggbf, p_w2bf, p_h2bf, NN, DH);
    k_gather<<<(NN + 1) / 2, dim3(128, 2)>>>(p_h2bf, bg2, p_hbf);  // reuse g_hbf

    k_segmax<<<dim3(NG, 2), 128>>>(batch, p_hbf);
    k_head<<<(DFC + 31) / 32, 256>>>(p_pool, W1, b1, p_fc1, DFC, DH, 0, nullptr, nullptr);
    k_head<<<(DOUT + 31) / 32, 256>>>(p_fc1, W2, b2, out, DOUT, DFC, 1, gamma, beta);
}

// round 14
// speedup vs baseline: 1.0941x; 1.0941x over previous
#include <cuda_runtime.h>
#include <math.h>
#include <stdint.h>

#define NN   20000
#define NE   320000
#define NG   64
#define DIN  1280
#define DH   512
#define DFC  1024
#define DOUT 5000

// ---------------- scratch ----------------
__device__ uint16_t g_xbf  [NN * DIN];
__device__ uint16_t g_w1bf [DIN * DH];
__device__ uint16_t g_w2bf [DH * DH];
__device__ uint16_t g_hbf  [NN * DH];   // GEMM1 out; later reused as gather2 out
__device__ uint16_t g_aggbf[NN * DH];
__device__ uint16_t g_h2bf [NN * DH];
__device__ float    g_dinv [NN];
__device__ int      g_cnt  [NN];
__device__ int      g_rowptr[NN + 1];
__device__ int      g_cursor[NN];
__device__ int      g_csrsrc[NE];
__device__ float    g_pool[NG * DH];
__device__ float    g_fc1 [NG * DFC];
__device__ int      g_is64;

// ---------------- helpers ----------------
__device__ __forceinline__ uint32_t smem_u32(const void* p) {
    uint32_t a;
    asm("{ .reg .u64 t; cvta.to.shared.u64 t, %1; cvt.u32.u64 %0, t; }" : "=r"(a) : "l"(p));
    return a;
}
__device__ __forceinline__ uint32_t pack_bf16(float lo, float hi) {
    uint32_t r;
    asm("cvt.rn.bf16x2.f32 %0, %1, %2;" : "=r"(r) : "f"(hi), "f"(lo));
    return r;
}
__device__ __forceinline__ float bf_lo(uint32_t u) { return __uint_as_float(u << 16); }
__device__ __forceinline__ float bf_hi(uint32_t u) { return __uint_as_float(u & 0xFFFF0000u); }

__device__ __forceinline__ void ldsm_x4(uint32_t* r, uint32_t addr) {
    asm volatile("ldmatrix.sync.aligned.m8n8.x4.shared.b16 {%0,%1,%2,%3}, [%4];"
        : "=r"(r[0]), "=r"(r[1]), "=r"(r[2]), "=r"(r[3]) : "r"(addr));
}
__device__ __forceinline__ void ldsm_x2t(uint32_t* r, uint32_t addr) {
    asm volatile("ldmatrix.sync.aligned.m8n8.x2.trans.shared.b16 {%0,%1}, [%2];"
        : "=r"(r[0]), "=r"(r[1]) : "r"(addr));
}
__device__ __forceinline__ void cpa16(uint32_t dst, const void* src, int valid) {
    asm volatile("cp.async.cg.shared.global [%0], [%1], 16, %2;"
        :: "r"(dst), "l"(src), "r"(valid ? 16 : 0));
}
#define CPA_COMMIT() asm volatile("cp.async.commit_group;" ::: "memory")
#define CPA_WAIT1()  asm volatile("cp.async.wait_group 1;" ::: "memory")

// ---------------- fused f32 -> bf16 conversion ----------------
#define N4_X  (NN * DIN / 4)
#define N4_W1 (DIN * DH / 4)
#define N4_W2 (DH * DH / 4)
#define N4_ALL (N4_X + N4_W1 + N4_W2)

__global__ void k_cvt_all(const float4* __restrict__ x,
                          const float4* __restrict__ w1,
                          const float4* __restrict__ w2)
{
    int i = blockIdx.x * blockDim.x + threadIdx.x;
    if (i >= N4_ALL) return;
    const float4* src;
    uint2* dst;
    int off;
    if (i < N4_X) {
        src = x;  dst = (uint2*)g_xbf;  off = i;
    } else if (i < N4_X + N4_W1) {
        src = w1; dst = (uint2*)g_w1bf; off = i - N4_X;
    } else {
        src = w2; dst = (uint2*)g_w2bf; off = i - N4_X - N4_W1;
    }
    float4 v = src[off];
    dst[off] = make_uint2(pack_bf16(v.x, v.y), pack_bf16(v.z, v.w));
}

// ---------------- dtype detection ----------------
__global__ void k_detect(const void* ei) {
    const long long* p = (const long long*)ei;
    int ok = 1;
#pragma unroll
    for (int i = 0; i < 8; i++) {
        long long v = p[i];
        if (v < 0 || v >= NN) ok = 0;
    }
    g_is64 = ok;
}
__device__ __forceinline__ int idx_at(const void* p, long long i) {
    return g_is64 ? (int)((const long long*)p)[i] : ((const int*)p)[i];
}

// ---------------- degree / CSR ----------------
__global__ void k_zero_cnt() {
    int i = blockIdx.x * blockDim.x + threadIdx.x;
    if (i < NN) g_cnt[i] = 0;
}
__global__ void k_deg(const void* __restrict__ ei) {
    int e = blockIdx.x * blockDim.x + threadIdx.x;
    if (e < NE) atomicAdd(&g_cnt[idx_at(ei, (long long)NE + e)], 1);
}

#define SCAN_T   1024
#define SCAN_CH  20
__global__ void __launch_bounds__(SCAN_T) k_scan() {
    __shared__ int s[SCAN_T];
    int tid = threadIdx.x;
    int base = tid * SCAN_CH;
    int local[SCAN_CH];
    int cnts[SCAN_CH];
    int sum = 0;
#pragma unroll
    for (int i = 0; i < SCAN_CH; i++) {
        int idx = base + i;
        int v = (idx < NN) ? g_cnt[idx] : 0;
        cnts[i] = v;
        local[i] = sum;
        sum += v;
    }
    s[tid] = sum;
    __syncthreads();
    for (int off = 1; off < SCAN_T; off <<= 1) {
        int v = (tid >= off) ? s[tid - off] : 0;
        __syncthreads();
        if (tid >= off) s[tid] += v;
        __syncthreads();
    }
    int pre = (tid > 0) ? s[tid - 1] : 0;
#pragma unroll
    for (int i = 0; i < SCAN_CH; i++) {
        int idx = base + i;
        if (idx < NN) {
            int v = pre + local[i];
            g_rowptr[idx] = v;
            g_cursor[idx] = v;
            g_dinv[idx] = rsqrtf((float)cnts[i] + 1.0f);
        }
    }
    if (tid == SCAN_T - 1) g_rowptr[NN] = NE;
}
__global__ void k_fill(const void* __restrict__ ei) {
    int e = blockIdx.x * blockDim.x + threadIdx.x;
    if (e < NE) {
        int src, dst;
        if (g_is64) {
            const long long* p = (const long long*)ei;
            src = (int)p[e]; dst = (int)p[NE + e];
        } else {
            const int* p = (const int*)ei;
            src = p[e]; dst = p[NE + e];
        }
        g_csrsrc[atomicAdd(&g_cursor[dst], 1)] = src;
    }
}

// ---------------- bf16 mma GEMM, cp.async 3-stage pipeline (BK=32, proven) ----------------
#define A_STR 40
#define B_STR 136
#define ABYTES (128 * A_STR * 2)
#define BBYTES (32 * B_STR * 2)
#define STG    (ABYTES + BBYTES)
#define GEMM_SMEM (3 * STG)

__global__ void __launch_bounds__(256, 2) k_gemm_bf16(
    const uint16_t* __restrict__ A, const uint16_t* __restrict__ B,
    uint16_t* __restrict__ Cb, int M, int K)
{
    extern __shared__ __align__(16) uint16_t smem[];
    const uint32_t sb = smem_u32(smem);

    const int tid  = threadIdx.x;
    const int wid  = tid >> 5;
    const int lane = tid & 31;
    const int wm   = wid >> 2;
    const int wn   = wid & 3;
    const int n0   = blockIdx.x * 128;
    const int m0   = blockIdx.y * 128;
    const int NIT  = K >> 5;

    const int ar0 = (tid >> 2);
    const int ac0 = (tid & 3);
    const int br0 = (tid >> 4);
    const int bc0 = (tid & 15);

    auto load_tile = [&](int it, int stage) {
        const int k0 = it << 5;
        const uint32_t base = sb + stage * STG;
#pragma unroll
        for (int i = 0; i < 2; i++) {
            int row = ar0 + i * 64;
            uint32_t dst = base + row * (A_STR * 2) + ac0 * 16;
            const uint16_t* src = A + (size_t)(m0 + row) * K + k0 + ac0 * 8;
            cpa16(dst, src, (m0 + row) < M);
        }
#pragma unroll
        for (int i = 0; i < 2; i++) {
            int row = br0 + i * 16;
            uint32_t dst = base + ABYTES + row * (B_STR * 2) + bc0 * 16;
            const uint16_t* src = B + (size_t)(k0 + row) * DH + n0 + bc0 * 8;
            cpa16(dst, src, 1);
        }
    };

    float acc[4][4][4];
#pragma unroll
    for (int mi = 0; mi < 4; mi++)
#pragma unroll
        for (int ni = 0; ni < 4; ni++)
#pragma unroll
            for (int q = 0; q < 4; q++) acc[mi][ni][q] = 0.0f;

    load_tile(0, 0);
    CPA_COMMIT();
    if (NIT > 1) load_tile(1, 1);
    CPA_COMMIT();

    const int lr15 = lane & 15;
    const int lk8  = (lane >> 4) << 3;

    for (int it = 0; it < NIT; it++) {
        CPA_WAIT1();
        __syncthreads();

        int nxt = it + 2;
        if (nxt < NIT) load_tile(nxt, nxt % 3);
        CPA_COMMIT();

        const uint32_t aB = sb + (it % 3) * STG;
        const uint32_t bB = aB + ABYTES;

#pragma unroll
        for (int ks = 0; ks < 2; ks++) {
            const int kb = ks * 16;
            uint32_t af[4][4], bfr[4][2];
#pragma unroll
            for (int mi = 0; mi < 4; mi++) {
                uint32_t ad = aB +
                    (uint32_t)(((wm * 64 + mi * 16 + lr15) * A_STR + kb + lk8) * 2);
                ldsm_x4(af[mi], ad);
            }
#pragma unroll
            for (int ni = 0; ni < 4; ni++) {
                uint32_t bd = bB +
                    (uint32_t)(((kb + lr15) * B_STR + wn * 32 + ni * 8) * 2);
                ldsm_x2t(bfr[ni], bd);
            }
#pragma unroll
            for (int mi = 0; mi < 4; mi++)
#pragma unroll
                for (int ni = 0; ni < 4; ni++) {
                    asm volatile(
                        "mma.sync.aligned.m16n8k16.row.col.f32.bf16.bf16.f32 "
                        "{%0,%1,%2,%3}, {%4,%5,%6,%7}, {%8,%9}, {%0,%1,%2,%3};"
                        : "+f"(acc[mi][ni][0]), "+f"(acc[mi][ni][1]),
                          "+f"(acc[mi][ni][2]), "+f"(acc[mi][ni][3])
                        : "r"(af[mi][0]), "r"(af[mi][1]), "r"(af[mi][2]), "r"(af[mi][3]),
                          "r"(bfr[ni][0]), "r"(bfr[ni][1]));
                }
        }
    }

    const int r = lane >> 2;
    const int c = lane & 3;
#pragma unroll
    for (int mi = 0; mi < 4; mi++) {
        int row = m0 + wm * 64 + mi * 16 + r;
#pragma unroll
        for (int ni = 0; ni < 4; ni++) {
            int col = n0 + wn * 32 + ni * 8 + c * 2;
            if (row < M)
                *(uint32_t*)(Cb + (size_t)row * DH + col) =
                    pack_bf16(acc[mi][ni][0], acc[mi][ni][1]);
            if (row + 8 < M)
                *(uint32_t*)(Cb + (size_t)(row + 8) * DH + col) =
                    pack_bf16(acc[mi][ni][2], acc[mi][ni][3]);
        }
    }
}

// ---------------- CSR gather (bf16 in, bf16+relu out), 8-way unrolled ----------------
__global__ void __launch_bounds__(256) k_gather(
    const uint16_t* __restrict__ h, const float* __restrict__ bias,
    uint16_t* __restrict__ ob)
{
    int n = blockIdx.x * 2 + threadIdx.y;
    if (n >= NN) return;
    int s = g_rowptr[n];
    int e = g_rowptr[n + 1];
    float dn = g_dinv[n];
    int c = threadIdx.x * 4;

    uint2 u = *(const uint2*)(h + (size_t)n * DH + c);
    float d2 = dn * dn;
    float a0 = bf_lo(u.x) * d2, a1 = bf_hi(u.x) * d2;
    float a2 = bf_lo(u.y) * d2, a3 = bf_hi(u.y) * d2;

    int j = s;
    for (; j + 7 < e; j += 8) {
        int sv[8];
        float cv[8];
        uint2 uv[8];
#pragma unroll
        for (int q = 0; q < 8; q++) sv[q] = g_csrsrc[j + q];
#pragma unroll
        for (int q = 0; q < 8; q++) cv[q] = g_dinv[sv[q]] * dn;
#pragma unroll
        for (int q = 0; q < 8; q++)
            uv[q] = *(const uint2*)(h + (size_t)sv[q] * DH + c);
#pragma unroll
        for (int q = 0; q < 8; q++) {
            a0 = fmaf(bf_lo(uv[q].x), cv[q], a0);
            a1 = fmaf(bf_hi(uv[q].x), cv[q], a1);
            a2 = fmaf(bf_lo(uv[q].y), cv[q], a2);
            a3 = fmaf(bf_hi(uv[q].y), cv[q], a3);
        }
    }
    for (; j < e; j++) {
        int s0 = g_csrsrc[j];
        float c0 = g_dinv[s0] * dn;
        uint2 u0 = *(const uint2*)(h + (size_t)s0 * DH + c);
        a0 = fmaf(bf_lo(u0.x), c0, a0); a1 = fmaf(bf_hi(u0.x), c0, a1);
        a2 = fmaf(bf_lo(u0.y), c0, a2); a3 = fmaf(bf_hi(u0.y), c0, a3);
    }

    float4 b = *(const float4*)(bias + c);
    a0 = fmaxf(a0 + b.x, 0.f); a1 = fmaxf(a1 + b.y, 0.f);
    a2 = fmaxf(a2 + b.z, 0.f); a3 = fmaxf(a3 + b.w, 0.f);
    *(uint2*)(ob + (size_t)n * DH + c) =
        make_uint2(pack_bf16(a0, a1), pack_bf16(a2, a3));
}

// ---------------- segment max over bf16 rows ----------------
__device__ __forceinline__ int lower_bound_batch(const void* batch, int val) {
    int lo = 0, hi = NN;
    while (lo < hi) {
        int mid = (lo + hi) >> 1;
        if (idx_at(batch, mid) < val) lo = mid + 1; else hi = mid;
    }
    return lo;
}
// grid (NG, 2), 128 thr; each thread = one uint32 (2 cols)
__global__ void k_segmax(const void* __restrict__ batch, const uint16_t* __restrict__ hb) {
    int g = blockIdx.x;
    int cw = blockIdx.y * 128 + threadIdx.x;   // word index 0..255
    int s = lower_bound_batch(batch, g);
    int e = lower_bound_batch(batch, g + 1);
    const uint32_t* hw = (const uint32_t*)hb;
    float m0 = 0.f, m1 = 0.f, m2 = 0.f, m3 = 0.f;
    int n = s;
    for (; n + 1 < e; n += 2) {
        uint32_t u0 = hw[(size_t)n * (DH / 2) + cw];
        uint32_t u1 = hw[(size_t)(n + 1) * (DH / 2) + cw];
        m0 = fmaxf(m0, bf_lo(u0)); m1 = fmaxf(m1, bf_hi(u0));
        m2 = fmaxf(m2, bf_lo(u1)); m3 = fmaxf(m3, bf_hi(u1));
    }
    if (n < e) {
        uint32_t u0 = hw[(size_t)n * (DH / 2) + cw];
        m0 = fmaxf(m0, bf_lo(u0)); m1 = fmaxf(m1, bf_hi(u0));
    }
    g_pool[g * DH + cw * 2]     = fmaxf(m0, m2);
    g_pool[g * DH + cw * 2 + 1] = fmaxf(m1, m3);
}

// ---------------- FC head ----------------
__global__ void __launch_bounds__(256) k_head(
    const float* __restrict__ A, const float* __restrict__ B,
    const float* __restrict__ bias, float* __restrict__ C,
    int N, int K, int mode,
    const float* __restrict__ gamma, const float* __restrict__ beta)
{
    const int BKh = 32, BNh = 32;
    __shared__ float As[BKh][64];
    __shared__ float Bs[BKh][BNh];

    int tid = threadIdx.x;
    int colBase = blockIdx.x * BNh;
    int ty = tid >> 4, tx = tid & 15;

    float acc[4][2] = {{0.f, 0.f}, {0.f, 0.f}, {0.f, 0.f}, {0.f, 0.f}};

    for (int k0 = 0; k0 < K; k0 += BKh) {
        __syncthreads();
#pragma unroll
        for (int l = 0; l < 8; l++) {
            int idx = tid * 8 + l;
            int m = idx >> 5, k = idx & 31;
            As[k][m] = A[(size_t)m * K + k0 + k];
        }
#pragma unroll
        for (int l = 0; l < 4; l++) {
            int idx = tid * 4 + l;
            int k = idx >> 5, n = idx & 31;
            int col = colBase + n;
            Bs[k][n] = (col < N) ? B[(size_t)(k0 + k) * N + col] : 0.f;
        }
        __syncthreads();
#pragma unroll
        for (int k = 0; k < BKh; k++) {
            float ra2[4], rb2[2];
#pragma unroll
            for (int i = 0; i < 4; i++) ra2[i] = As[k][ty * 4 + i];
#pragma unroll
            for (int j = 0; j < 2; j++) rb2[j] = Bs[k][tx * 2 + j];
#pragma unroll
            for (int i = 0; i < 4; i++)
#pragma unroll
                for (int j = 0; j < 2; j++)
                    acc[i][j] = fmaf(ra2[i], rb2[j], acc[i][j]);
        }
    }

    const float bninv = rsqrtf(1.0f + 1e-5f);
#pragma unroll
    for (int i = 0; i < 4; i++) {
#pragma unroll
        for (int j = 0; j < 2; j++) {
            int row = ty * 4 + i;
            int col = colBase + tx * 2 + j;
            if (col < N) {
                float z = acc[i][j] + bias[col];
                if (mode == 0) {
                    z = fmaxf(z, 0.f);
                } else {
                    z = z * gamma[col] * bninv + beta[col];
                    z = 1.0f / (1.0f + expf(-z));
                }
                C[(size_t)row * N + col] = z;
            }
        }
    }
}

// ---------------- host ----------------
extern "C" void kernel_launch(void* const* d_in, const int* in_sizes, int n_in,
                              void* d_out, int out_size)
{
    const float* x     = (const float*)d_in[0];
    const void*  ei    = d_in[1];
    const void*  batch = d_in[2];
    const float* Wg1   = (const float*)d_in[3];
    const float* bg1   = (const float*)d_in[4];
    const float* Wg2   = (const float*)d_in[5];
    const float* bg2   = (const float*)d_in[6];
    const float* W1    = (const float*)d_in[7];
    const float* b1    = (const float*)d_in[8];
    const float* W2    = (const float*)d_in[9];
    const float* b2    = (const float*)d_in[10];
    const float* gamma = (const float*)d_in[11];
    const float* beta  = (const float*)d_in[12];
    float* out = (float*)d_out;

    uint16_t *p_xbf, *p_w1bf, *p_w2bf, *p_hbf, *p_aggbf, *p_h2bf;
    float *p_pool, *p_fc1;
    cudaGetSymbolAddress((void**)&p_xbf,   g_xbf);
    cudaGetSymbolAddress((void**)&p_w1bf,  g_w1bf);
    cudaGetSymbolAddress((void**)&p_w2bf,  g_w2bf);
    cudaGetSymbolAddress((void**)&p_hbf,   g_hbf);
    cudaGetSymbolAddress((void**)&p_aggbf, g_aggbf);
    cudaGetSymbolAddress((void**)&p_h2bf,  g_h2bf);
    cudaGetSymbolAddress((void**)&p_pool,  g_pool);
    cudaGetSymbolAddress((void**)&p_fc1,   g_fc1);

    cudaFuncSetAttribute(k_gemm_bf16,
        cudaFuncAttributeMaxDynamicSharedMemorySize, GEMM_SMEM);

    static cudaStream_t sB = nullptr;
    static cudaEvent_t evFork = nullptr, evJoin = nullptr;
    if (!sB) {
        cudaStreamCreateWithFlags(&sB, cudaStreamNonBlocking);
        cudaEventCreateWithFlags(&evFork, cudaEventDisableTiming);
        cudaEventCreateWithFlags(&evJoin, cudaEventDisableTiming);
    }

    // ---- fork: CSR build chain on sB, concurrent with cvt+GEMM1 on main ----
    cudaEventRecord(evFork, 0);
    cudaStreamWaitEvent(sB, evFork, 0);

    k_detect<<<1, 1, 0, sB>>>(ei);
    k_zero_cnt<<<(NN + 255) / 256, 256, 0, sB>>>();
    k_deg<<<(NE + 255) / 256, 256, 0, sB>>>(ei);
    k_scan<<<1, SCAN_T, 0, sB>>>();
    k_fill<<<(NE + 255) / 256, 256, 0, sB>>>(ei);
    cudaEventRecord(evJoin, sB);

    // main stream: conversions + GEMM1 (independent of CSR)
    k_cvt_all<<<(N4_ALL + 255) / 256, 256>>>((const float4*)x, (const float4*)Wg1,
                                             (const float4*)Wg2);
    dim3 gg(DH / 128, (NN + 127) / 128);
    k_gemm_bf16<<<gg, 256, GEMM_SMEM>>>(p_xbf, p_w1bf, p_hbf, NN, DIN);

    // ---- join ----
    cudaStreamWaitEvent(0, evJoin, 0);

    k_gather<<<(NN + 1) / 2, dim3(128, 2)>>>(p_hbf, bg1, p_aggbf);
    k_gemm_bf16<<<gg, 256, GEMM_SMEM>>>(p_aggbf, p_w2bf, p_h2bf, NN, DH);
    k_gather<<<(NN + 1) / 2, dim3(128, 2)>>>(p_h2bf, bg2, p_hbf);  // reuse g_hbf

    k_segmax<<<dim3(NG, 2), 128>>>(batch, p_hbf);
    k_head<<<(DFC + 31) / 32, 256>>>(p_pool, W1, b1, p_fc1, DFC, DH, 0, nullptr, nullptr);
    k_head<<<(DOUT + 31) / 32, 256>>>(p_fc1, W2, b2, out, DOUT, DFC, 1, gamma, beta);
}

// round 15
// speedup vs baseline: 1.1027x; 1.0079x over previous
#include <cuda_runtime.h>
#include <math.h>
#include <stdint.h>

#define NN   20000
#define NE   320000
#define NG   64
#define DIN  1280
#define DH   512
#define DFC  1024
#define DOUT 5000

// ---------------- scratch ----------------
__device__ uint16_t g_w1bf [DIN * DH];
__device__ uint16_t g_w2bf [DH * DH];
__device__ uint16_t g_hbf  [NN * DH];   // GEMM1 out; later reused as gather2 out
__device__ uint16_t g_aggbf[NN * DH];
__device__ uint16_t g_h2bf [NN * DH];
__device__ float    g_dinv [NN];
__device__ int      g_cnt  [NN];
__device__ int      g_rowptr[NN + 1];
__device__ int      g_cursor[NN];
__device__ int      g_csrsrc[NE];
__device__ float    g_pool[NG * DH];
__device__ float    g_fc1 [NG * DFC];
__device__ int      g_is64;

// ---------------- helpers ----------------
__device__ __forceinline__ uint32_t smem_u32(const void* p) {
    uint32_t a;
    asm("{ .reg .u64 t; cvta.to.shared.u64 t, %1; cvt.u32.u64 %0, t; }" : "=r"(a) : "l"(p));
    return a;
}
__device__ __forceinline__ uint32_t pack_bf16(float lo, float hi) {
    uint32_t r;
    asm("cvt.rn.bf16x2.f32 %0, %1, %2;" : "=r"(r) : "f"(hi), "f"(lo));
    return r;
}
__device__ __forceinline__ float bf_lo(uint32_t u) { return __uint_as_float(u << 16); }
__device__ __forceinline__ float bf_hi(uint32_t u) { return __uint_as_float(u & 0xFFFF0000u); }

__device__ __forceinline__ void ldsm_x4(uint32_t* r, uint32_t addr) {
    asm volatile("ldmatrix.sync.aligned.m8n8.x4.shared.b16 {%0,%1,%2,%3}, [%4];"
        : "=r"(r[0]), "=r"(r[1]), "=r"(r[2]), "=r"(r[3]) : "r"(addr));
}
__device__ __forceinline__ void ldsm_x2t(uint32_t* r, uint32_t addr) {
    asm volatile("ldmatrix.sync.aligned.m8n8.x2.trans.shared.b16 {%0,%1}, [%2];"
        : "=r"(r[0]), "=r"(r[1]) : "r"(addr));
}
__device__ __forceinline__ void cpa16(uint32_t dst, const void* src, int valid) {
    asm volatile("cp.async.cg.shared.global [%0], [%1], 16, %2;"
        :: "r"(dst), "l"(src), "r"(valid ? 16 : 0));
}
#define CPA_COMMIT() asm volatile("cp.async.commit_group;" ::: "memory")
#define CPA_WAIT1()  asm volatile("cp.async.wait_group 1;" ::: "memory")

// ---------------- f32 -> bf16 conversion (weights only now) ----------------
#define N4_W1 (DIN * DH / 4)
#define N4_W2 (DH * DH / 4)
#define N4_W  (N4_W1 + N4_W2)

__global__ void k_cvt_w(const float4* __restrict__ w1, const float4* __restrict__ w2) {
    int i = blockIdx.x * blockDim.x + threadIdx.x;
    if (i >= N4_W) return;
    const float4* src;
    uint2* dst;
    int off;
    if (i < N4_W1) {
        src = w1; dst = (uint2*)g_w1bf; off = i;
    } else {
        src = w2; dst = (uint2*)g_w2bf; off = i - N4_W1;
    }
    float4 v = src[off];
    dst[off] = make_uint2(pack_bf16(v.x, v.y), pack_bf16(v.z, v.w));
}

// ---------------- dtype detection ----------------
__global__ void k_detect(const void* ei) {
    const long long* p = (const long long*)ei;
    int ok = 1;
#pragma unroll
    for (int i = 0; i < 8; i++) {
        long long v = p[i];
        if (v < 0 || v >= NN) ok = 0;
    }
    g_is64 = ok;
}
__device__ __forceinline__ int idx_at(const void* p, long long i) {
    return g_is64 ? (int)((const long long*)p)[i] : ((const int*)p)[i];
}

// ---------------- degree / CSR ----------------
__global__ void k_zero_cnt() {
    int i = blockIdx.x * blockDim.x + threadIdx.x;
    if (i < NN) g_cnt[i] = 0;
}
__global__ void k_deg(const void* __restrict__ ei) {
    int e = blockIdx.x * blockDim.x + threadIdx.x;
    if (e < NE) atomicAdd(&g_cnt[idx_at(ei, (long long)NE + e)], 1);
}

#define SCAN_T   1024
#define SCAN_CH  20
__global__ void __launch_bounds__(SCAN_T) k_scan() {
    __shared__ int s[SCAN_T];
    int tid = threadIdx.x;
    int base = tid * SCAN_CH;
    int local[SCAN_CH];
    int cnts[SCAN_CH];
    int sum = 0;
#pragma unroll
    for (int i = 0; i < SCAN_CH; i++) {
        int idx = base + i;
        int v = (idx < NN) ? g_cnt[idx] : 0;
        cnts[i] = v;
        local[i] = sum;
        sum += v;
    }
    s[tid] = sum;
    __syncthreads();
    for (int off = 1; off < SCAN_T; off <<= 1) {
        int v = (tid >= off) ? s[tid - off] : 0;
        __syncthreads();
        if (tid >= off) s[tid] += v;
        __syncthreads();
    }
    int pre = (tid > 0) ? s[tid - 1] : 0;
#pragma unroll
    for (int i = 0; i < SCAN_CH; i++) {
        int idx = base + i;
        if (idx < NN) {
            int v = pre + local[i];
            g_rowptr[idx] = v;
            g_cursor[idx] = v;
            g_dinv[idx] = rsqrtf((float)cnts[i] + 1.0f);
        }
    }
    if (tid == SCAN_T - 1) g_rowptr[NN] = NE;
}
__global__ void k_fill(const void* __restrict__ ei) {
    int e = blockIdx.x * blockDim.x + threadIdx.x;
    if (e < NE) {
        int src, dst;
        if (g_is64) {
            const long long* p = (const long long*)ei;
            src = (int)p[e]; dst = (int)p[NE + e];
        } else {
            const int* p = (const int*)ei;
            src = p[e]; dst = p[NE + e];
        }
        g_csrsrc[atomicAdd(&g_cursor[dst], 1)] = src;
    }
}

// ---------------- bf16 mma GEMM, cp.async 3-stage pipeline (BK=32) ----------------
// AF32=1: A is fp32 in gmem, loaded via LDG + cvt + STS (reg double-buffered).
// AF32=0: A is bf16 in gmem, loaded via cp.async.
#define A_STR 40
#define B_STR 136
#define ABYTES (128 * A_STR * 2)
#define BBYTES (32 * B_STR * 2)
#define STG    (ABYTES + BBYTES)
#define GEMM_SMEM (3 * STG)

template <int AF32>
__global__ void __launch_bounds__(256, 2) k_gemm_bf16(
    const void* __restrict__ Av, const uint16_t* __restrict__ B,
    uint16_t* __restrict__ Cb, int M, int K)
{
    extern __shared__ __align__(16) uint16_t smem[];
    const uint32_t sb = smem_u32(smem);

    const int tid  = threadIdx.x;
    const int wid  = tid >> 5;
    const int lane = tid & 31;
    const int wm   = wid >> 2;
    const int wn   = wid & 3;
    const int n0   = blockIdx.x * 128;
    const int m0   = blockIdx.y * 128;
    const int NIT  = K >> 5;

    // cp.async A loader mapping (AF32=0)
    const int ar0 = (tid >> 2);
    const int ac0 = (tid & 3);
    // LDG A loader mapping (AF32=1): 2 thr/row, 16 floats each
    const int alm = tid >> 1;
    const int akh = (tid & 1) * 16;
    const bool aval = (m0 + alm) < M;
    const float* Af = (const float*)Av + (size_t)(m0 + alm) * K + akh;
    // B loader
    const int br0 = (tid >> 4);
    const int bc0 = (tid & 15);

    auto load_B = [&](int it, int stage) {
        const int k0 = it << 5;
        const uint32_t base = sb + stage * STG + ABYTES;
#pragma unroll
        for (int i = 0; i < 2; i++) {
            int row = br0 + i * 16;
            uint32_t dst = base + row * (B_STR * 2) + bc0 * 16;
            const uint16_t* src = B + (size_t)(k0 + row) * DH + n0 + bc0 * 8;
            cpa16(dst, src, 1);
        }
    };
    auto load_A_cp = [&](int it, int stage) {
        const int k0 = it << 5;
        const uint32_t base = sb + stage * STG;
        const uint16_t* Ah = (const uint16_t*)Av;
#pragma unroll
        for (int i = 0; i < 2; i++) {
            int row = ar0 + i * 64;
            uint32_t dst = base + row * (A_STR * 2) + ac0 * 16;
            const uint16_t* src = Ah + (size_t)(m0 + row) * K + k0 + ac0 * 8;
            cpa16(dst, src, (m0 + row) < M);
        }
    };

    float4 fa[4];
    auto ldg_A = [&](int it) {
        const float4* p = (const float4*)(Af + (it << 5));
        if (aval) {
#pragma unroll
            for (int i = 0; i < 4; i++) fa[i] = p[i];
        } else {
#pragma unroll
            for (int i = 0; i < 4; i++) fa[i] = make_float4(0.f, 0.f, 0.f, 0.f);
        }
    };
    auto sts_A = [&](int stage) {
        uint32_t ua[8];
#pragma unroll
        for (int i = 0; i < 4; i++) {
            ua[i * 2]     = pack_bf16(fa[i].x, fa[i].y);
            ua[i * 2 + 1] = pack_bf16(fa[i].z, fa[i].w);
        }
        uint16_t* dst = smem + stage * (STG / 2) + alm * A_STR + akh;
        *(uint4*)dst       = make_uint4(ua[0], ua[1], ua[2], ua[3]);
        *(uint4*)(dst + 8) = make_uint4(ua[4], ua[5], ua[6], ua[7]);
    };

    float acc[4][4][4];
#pragma unroll
    for (int mi = 0; mi < 4; mi++)
#pragma unroll
        for (int ni = 0; ni < 4; ni++)
#pragma unroll
            for (int q = 0; q < 4; q++) acc[mi][ni][q] = 0.0f;

    // prologue
    if (AF32) {
        ldg_A(0);
        load_B(0, 0);
        CPA_COMMIT();
        if (NIT > 1) load_B(1, 1);
        CPA_COMMIT();
    } else {
        load_A_cp(0, 0); load_B(0, 0);
        CPA_COMMIT();
        if (NIT > 1) { load_A_cp(1, 1); load_B(1, 1); }
        CPA_COMMIT();
    }

    const int lr15 = lane & 15;
    const int lk8  = (lane >> 4) << 3;

    for (int it = 0; it < NIT; it++) {
        CPA_WAIT1();
        if (AF32) sts_A(it % 3);
        __syncthreads();

        int nxt = it + 2;
        if (AF32) {
            if (it + 1 < NIT) ldg_A(it + 1);
            if (nxt < NIT) load_B(nxt, nxt % 3);
        } else {
            if (nxt < NIT) { load_A_cp(nxt, nxt % 3); load_B(nxt, nxt % 3); }
        }
        CPA_COMMIT();

        const uint32_t aB = sb + (it % 3) * STG;
        const uint32_t bB = aB + ABYTES;

#pragma unroll
        for (int ks = 0; ks < 2; ks++) {
            const int kb = ks * 16;
            uint32_t af[4][4], bfr[4][2];
#pragma unroll
            for (int mi = 0; mi < 4; mi++) {
                uint32_t ad = aB +
                    (uint32_t)(((wm * 64 + mi * 16 + lr15) * A_STR + kb + lk8) * 2);
                ldsm_x4(af[mi], ad);
            }
#pragma unroll
            for (int ni = 0; ni < 4; ni++) {
                uint32_t bd = bB +
                    (uint32_t)(((kb + lr15) * B_STR + wn * 32 + ni * 8) * 2);
                ldsm_x2t(bfr[ni], bd);
            }
#pragma unroll
            for (int mi = 0; mi < 4; mi++)
#pragma unroll
                for (int ni = 0; ni < 4; ni++) {
                    asm volatile(
                        "mma.sync.aligned.m16n8k16.row.col.f32.bf16.bf16.f32 "
                        "{%0,%1,%2,%3}, {%4,%5,%6,%7}, {%8,%9}, {%0,%1,%2,%3};"
                        : "+f"(acc[mi][ni][0]), "+f"(acc[mi][ni][1]),
                          "+f"(acc[mi][ni][2]), "+f"(acc[mi][ni][3])
                        : "r"(af[mi][0]), "r"(af[mi][1]), "r"(af[mi][2]), "r"(af[mi][3]),
                          "r"(bfr[ni][0]), "r"(bfr[ni][1]));
                }
        }
    }

    const int r = lane >> 2;
    const int c = lane & 3;
#pragma unroll
    for (int mi = 0; mi < 4; mi++) {
        int row = m0 + wm * 64 + mi * 16 + r;
#pragma unroll
        for (int ni = 0; ni < 4; ni++) {
            int col = n0 + wn * 32 + ni * 8 + c * 2;
            if (row < M)
                *(uint32_t*)(Cb + (size_t)row * DH + col) =
                    pack_bf16(acc[mi][ni][0], acc[mi][ni][1]);
            if (row + 8 < M)
                *(uint32_t*)(Cb + (size_t)(row + 8) * DH + col) =
                    pack_bf16(acc[mi][ni][2], acc[mi][ni][3]);
        }
    }
}

// ---------------- CSR gather (bf16 in, bf16+relu out), 8-way unrolled ----------------
__global__ void __launch_bounds__(256) k_gather(
    const uint16_t* __restrict__ h, const float* __restrict__ bias,
    uint16_t* __restrict__ ob)
{
    int n = blockIdx.x * 2 + threadIdx.y;
    if (n >= NN) return;
    int s = g_rowptr[n];
    int e = g_rowptr[n + 1];
    float dn = g_dinv[n];
    int c = threadIdx.x * 4;

    uint2 u = *(const uint2*)(h + (size_t)n * DH + c);
    float d2 = dn * dn;
    float a0 = bf_lo(u.x) * d2, a1 = bf_hi(u.x) * d2;
    float a2 = bf_lo(u.y) * d2, a3 = bf_hi(u.y) * d2;

    int j = s;
    for (; j + 7 < e; j += 8) {
        int sv[8];
        float cv[8];
        uint2 uv[8];
#pragma unroll
        for (int q = 0; q < 8; q++) sv[q] = g_csrsrc[j + q];
#pragma unroll
        for (int q = 0; q < 8; q++) cv[q] = g_dinv[sv[q]] * dn;
#pragma unroll
        for (int q = 0; q < 8; q++)
            uv[q] = *(const uint2*)(h + (size_t)sv[q] * DH + c);
#pragma unroll
        for (int q = 0; q < 8; q++) {
            a0 = fmaf(bf_lo(uv[q].x), cv[q], a0);
            a1 = fmaf(bf_hi(uv[q].x), cv[q], a1);
            a2 = fmaf(bf_lo(uv[q].y), cv[q], a2);
            a3 = fmaf(bf_hi(uv[q].y), cv[q], a3);
        }
    }
    for (; j < e; j++) {
        int s0 = g_csrsrc[j];
        float c0 = g_dinv[s0] * dn;
        uint2 u0 = *(const uint2*)(h + (size_t)s0 * DH + c);
        a0 = fmaf(bf_lo(u0.x), c0, a0); a1 = fmaf(bf_hi(u0.x), c0, a1);
        a2 = fmaf(bf_lo(u0.y), c0, a2); a3 = fmaf(bf_hi(u0.y), c0, a3);
    }

    float4 b = *(const float4*)(bias + c);
    a0 = fmaxf(a0 + b.x, 0.f); a1 = fmaxf(a1 + b.y, 0.f);
    a2 = fmaxf(a2 + b.z, 0.f); a3 = fmaxf(a3 + b.w, 0.f);
    *(uint2*)(ob + (size_t)n * DH + c) =
        make_uint2(pack_bf16(a0, a1), pack_bf16(a2, a3));
}

// ---------------- segment max over bf16 rows ----------------
__device__ __forceinline__ int lower_bound_batch(const void* batch, int val) {
    int lo = 0, hi = NN;
    while (lo < hi) {
        int mid = (lo + hi) >> 1;
        if (idx_at(batch, mid) < val) lo = mid + 1; else hi = mid;
    }
    return lo;
}
__global__ void k_segmax(const void* __restrict__ batch, const uint16_t* __restrict__ hb) {
    int g = blockIdx.x;
    int cw = blockIdx.y * 128 + threadIdx.x;
    int s = lower_bound_batch(batch, g);
    int e = lower_bound_batch(batch, g + 1);
    const uint32_t* hw = (const uint32_t*)hb;
    float m0 = 0.f, m1 = 0.f, m2 = 0.f, m3 = 0.f;
    int n = s;
    for (; n + 1 < e; n += 2) {
        uint32_t u0 = hw[(size_t)n * (DH / 2) + cw];
        uint32_t u1 = hw[(size_t)(n + 1) * (DH / 2) + cw];
        m0 = fmaxf(m0, bf_lo(u0)); m1 = fmaxf(m1, bf_hi(u0));
        m2 = fmaxf(m2, bf_lo(u1)); m3 = fmaxf(m3, bf_hi(u1));
    }
    if (n < e) {
        uint32_t u0 = hw[(size_t)n * (DH / 2) + cw];
        m0 = fmaxf(m0, bf_lo(u0)); m1 = fmaxf(m1, bf_hi(u0));
    }
    g_pool[g * DH + cw * 2]     = fmaxf(m0, m2);
    g_pool[g * DH + cw * 2 + 1] = fmaxf(m1, m3);
}

// ---------------- FC head ----------------
__global__ void __launch_bounds__(256) k_head(
    const float* __restrict__ A, const float* __restrict__ B,
    const float* __restrict__ bias, float* __restrict__ C,
    int N, int K, int mode,
    const float* __restrict__ gamma, const float* __restrict__ beta)
{
    const int BKh = 32, BNh = 32;
    __shared__ float As[BKh][64];
    __shared__ float Bs[BKh][BNh];

    int tid = threadIdx.x;
    int colBase = blockIdx.x * BNh;
    int ty = tid >> 4, tx = tid & 15;

    float acc[4][2] = {{0.f, 0.f}, {0.f, 0.f}, {0.f, 0.f}, {0.f, 0.f}};

    for (int k0 = 0; k0 < K; k0 += BKh) {
        __syncthreads();
#pragma unroll
        for (int l = 0; l < 8; l++) {
            int idx = tid * 8 + l;
            int m = idx >> 5, k = idx & 31;
            As[k][m] = A[(size_t)m * K + k0 + k];
        }
#pragma unroll
        for (int l = 0; l < 4; l++) {
            int idx = tid * 4 + l;
            int k = idx >> 5, n = idx & 31;
            int col = colBase + n;
            Bs[k][n] = (col < N) ? B[(size_t)(k0 + k) * N + col] : 0.f;
        }
        __syncthreads();
#pragma unroll
        for (int k = 0; k < BKh; k++) {
            float ra2[4], rb2[2];
#pragma unroll
            for (int i = 0; i < 4; i++) ra2[i] = As[k][ty * 4 + i];
#pragma unroll
            for (int j = 0; j < 2; j++) rb2[j] = Bs[k][tx * 2 + j];
#pragma unroll
            for (int i = 0; i < 4; i++)
#pragma unroll
                for (int j = 0; j < 2; j++)
                    acc[i][j] = fmaf(ra2[i], rb2[j], acc[i][j]);
        }
    }

    const float bninv = rsqrtf(1.0f + 1e-5f);
#pragma unroll
    for (int i = 0; i < 4; i++) {
#pragma unroll
        for (int j = 0; j < 2; j++) {
            int row = ty * 4 + i;
            int col = colBase + tx * 2 + j;
            if (col < N) {
                float z = acc[i][j] + bias[col];
                if (mode == 0) {
                    z = fmaxf(z, 0.f);
                } else {
                    z = z * gamma[col] * bninv + beta[col];
                    z = 1.0f / (1.0f + expf(-z));
                }
                C[(size_t)row * N + col] = z;
            }
        }
    }
}

// ---------------- host ----------------
extern "C" void kernel_launch(void* const* d_in, const int* in_sizes, int n_in,
                              void* d_out, int out_size)
{
    const float* x     = (const float*)d_in[0];
    const void*  ei    = d_in[1];
    const void*  batch = d_in[2];
    const float* Wg1   = (const float*)d_in[3];
    const float* bg1   = (const float*)d_in[4];
    const float* Wg2   = (const float*)d_in[5];
    const float* bg2   = (const float*)d_in[6];
    const float* W1    = (const float*)d_in[7];
    const float* b1    = (const float*)d_in[8];
    const float* W2    = (const float*)d_in[9];
    const float* b2    = (const float*)d_in[10];
    const float* gamma = (const float*)d_in[11];
    const float* beta  = (const float*)d_in[12];
    float* out = (float*)d_out;

    uint16_t *p_w1bf, *p_w2bf, *p_hbf, *p_aggbf, *p_h2bf;
    float *p_pool, *p_fc1;
    cudaGetSymbolAddress((void**)&p_w1bf,  g_w1bf);
    cudaGetSymbolAddress((void**)&p_w2bf,  g_w2bf);
    cudaGetSymbolAddress((void**)&p_hbf,   g_hbf);
    cudaGetSymbolAddress((void**)&p_aggbf, g_aggbf);
    cudaGetSymbolAddress((void**)&p_h2bf,  g_h2bf);
    cudaGetSymbolAddress((void**)&p_pool,  g_pool);
    cudaGetSymbolAddress((void**)&p_fc1,   g_fc1);

    cudaFuncSetAttribute(k_gemm_bf16<0>,
        cudaFuncAttributeMaxDynamicSharedMemorySize, GEMM_SMEM);
    cudaFuncSetAttribute(k_gemm_bf16<1>,
        cudaFuncAttributeMaxDynamicSharedMemorySize, GEMM_SMEM);

    static cudaStream_t sB = nullptr;
    static cudaEvent_t evFork = nullptr, evJoin = nullptr;
    if (!sB) {
        cudaStreamCreateWithFlags(&sB, cudaStreamNonBlocking);
        cudaEventCreateWithFlags(&evFork, cudaEventDisableTiming);
        cudaEventCreateWithFlags(&evJoin, cudaEventDisableTiming);
    }

    // ---- fork: CSR build chain on sB, concurrent with cvt+GEMM1 on main ----
    cudaEventRecord(evFork, 0);
    cudaStreamWaitEvent(sB, evFork, 0);

    k_detect<<<1, 1, 0, sB>>>(ei);
    k_zero_cnt<<<(NN + 255) / 256, 256, 0, sB>>>();
    k_deg<<<(NE + 255) / 256, 256, 0, sB>>>(ei);
    k_scan<<<1, SCAN_T, 0, sB>>>();
    k_fill<<<(NE + 255) / 256, 256, 0, sB>>>(ei);
    cudaEventRecord(evJoin, sB);

    // main stream: weight conversions + GEMM1 (reads fp32 x directly)
    k_cvt_w<<<(N4_W + 255) / 256, 256>>>((const float4*)Wg1, (const float4*)Wg2);
    dim3 gg(DH / 128, (NN + 127) / 128);
    k_gemm_bf16<1><<<gg, 256, GEMM_SMEM>>>(x, p_w1bf, p_hbf, NN, DIN);

    // ---- join ----
    cudaStreamWaitEvent(0, evJoin, 0);

    k_gather<<<(NN + 1) / 2, dim3(128, 2)>>>(p_hbf, bg1, p_aggbf);
    k_gemm_bf16<0><<<gg, 256, GEMM_SMEM>>>(p_aggbf, p_w2bf, p_h2bf, NN, DH);
    k_gather<<<(NN + 1) / 2, dim3(128, 2)>>>(p_h2bf, bg2, p_hbf);  // reuse g_hbf

    k_segmax<<<dim3(NG, 2), 128>>>(batch, p_hbf);
    k_head<<<(DFC + 31) / 32, 256>>>(p_pool, W1, b1, p_fc1, DFC, DH, 0, nullptr, nullptr);
    k_head<<<(DOUT + 31) / 32, 256>>>(p_fc1, W2, b2, out, DOUT, DFC, 1, gamma, beta);
}